// round 6
// baseline (speedup 1.0000x reference)
#include <cuda_runtime.h>

// Bidirectional GRU, persistent kernel, round 6.
// 128 blocks = 2 dirs x 64 j-blocks (8 h-columns each), 128 threads.
// Thread = (2 batches, 2 h-columns): bg = tid & 31 (b = 2bg, 2bg+1),
// jp = tid >> 5 (cols jA, jA+1). Warp = 32 bg, same jp => weight LDS broadcast,
// amortized over 2 b. x(t), h(t-1) staged via smem per 128-k chunk.
// Packed fma.rn.f32x2 throughout.

#define T_STEPS 512
#define BATCH   64
#define HID     512
#define NBLK    128
#define THREADS 128
#define PAD_ROW 132              // 33 float4s/row: conflict-free LDS.128

#define OUT_ROW   1024           // 2H
#define OUT_TSTR  (BATCH * OUT_ROW)

__device__ unsigned g_count = 0;
__device__ unsigned g_gen   = 0;

__device__ __forceinline__ float sigmoidf_(float x) {
    return 1.0f / (1.0f + __expf(-x));
}

__device__ __forceinline__ float tanhf_(float x) {
    float xc = fminf(fmaxf(x, -15.f), 15.f);
    float e  = __expf(2.f * xc);
    return (e - 1.f) / (e + 1.f);
}

__device__ __forceinline__ void fma2(unsigned long long& d,
                                     unsigned long long a,
                                     unsigned long long b) {
    asm volatile("fma.rn.f32x2 %0, %1, %2, %0;" : "+l"(d) : "l"(a), "l"(b));
}

__device__ __forceinline__ float2 unpk(unsigned long long v) {
    float2 r;
    asm("mov.b64 {%0,%1}, %2;" : "=f"(r.x), "=f"(r.y) : "l"(v));
    return r;
}

__device__ __forceinline__ void grid_barrier() {
    __syncthreads();
    if (threadIdx.x == 0) {
        volatile unsigned* vgen = &g_gen;
        unsigned gen = *vgen;
        unsigned ticket = atomicAdd(&g_count, 1u);
        if (ticket == NBLK - 1u) {
            atomicExch(&g_count, 0u);
            __threadfence();
            atomicAdd(&g_gen, 1u);   // release
        } else {
            while (*vgen == gen) { __nanosleep(32); }
        }
    }
    __syncthreads();
}

extern "C" __global__ void __launch_bounds__(THREADS, 1)
gru_bidir_kernel(const float* __restrict__ inp,
                 const float* __restrict__ h0f,  const float* __restrict__ h0b,
                 const float* __restrict__ Wih_f, const float* __restrict__ Whh_f,
                 const float* __restrict__ bih_f, const float* __restrict__ bhh_f,
                 const float* __restrict__ Wih_b, const float* __restrict__ Whh_b,
                 const float* __restrict__ bih_b, const float* __restrict__ bhh_b,
                 float* __restrict__ out)
{
    extern __shared__ float smem[];
    float* ws = smem;                       // [6][8][512] weights = 24576 floats
    float* xs = smem + 6 * 8 * 512;         // [64][PAD_ROW]
    float* hs = xs + BATCH * PAD_ROW;       // [64][PAD_ROW]

    const int tid  = threadIdx.x;
    const int dir  = blockIdx.x >> 6;       // 0 = fwd, 1 = bwd
    const int jblk = blockIdx.x & 63;
    const int j0   = jblk * 8;

    const float* Wih = dir ? Wih_b : Wih_f;
    const float* Whh = dir ? Whh_b : Whh_f;
    const float* bih = dir ? bih_b : bih_f;
    const float* bhh = dir ? bhh_b : bhh_f;
    const float* h0  = dir ? h0b   : h0f;

    // ---- Weights to shared: set 0..2 = Wih(r,z,n), 3..5 = Whh(r,z,n) ----
    for (int i = tid; i < 6144; i += THREADS) {       // 6144 float4s
        int row = i >> 7;       // 0..47
        int c4  = i & 127;
        int set = row >> 3;
        int jj  = row & 7;
        const float* W = (set < 3) ? Wih : Whh;
        int g = (set < 3) ? set : (set - 3);
        ((float4*)ws)[i] =
            ((const float4*)(W + ((size_t)(g * HID + j0 + jj) << 9)))[c4];
    }

    const int bg = tid & 31;                // lane; 2 batches: 2bg, 2bg+1
    const int b0 = bg * 2;
    const int jp = tid >> 5;                // warp id 0..3; 2 cols
    const int jA = j0 + jp * 2;
    const int jchunk = j0 >> 7;
    const int j_in   = jA & 127;

    // weight row pointers: [set 0..5][jj 0..1]
    const float* wp[12];
    #pragma unroll
    for (int set = 0; set < 6; ++set)
        #pragma unroll
        for (int jj = 0; jj < 2; ++jj)
            wp[set * 2 + jj] = ws + ((set * 8 + jp * 2 + jj) << 9);

    float bR[2], bZ[2], bIN[2], bHN[2];
    #pragma unroll
    for (int jj = 0; jj < 2; ++jj) {
        int j = jA + jj;
        bR[jj]  = bih[j]           + bhh[j];
        bZ[jj]  = bih[HID + j]     + bhh[HID + j];
        bIN[jj] = bih[2 * HID + j];
        bHN[jj] = bhh[2 * HID + j];
    }

    float* hT_out = out + (size_t)T_STEPS * OUT_TSTR + (size_t)dir * (BATCH * HID);

    __syncthreads();

    for (int s = 0; s < T_STEPS; ++s) {
        const int t  = dir ? (T_STEPS - 1 - s) : s;
        const int tp = dir ? (t + 1) : (t - 1);

        const float* hgbase;
        int hstr;
        if (s == 0) { hgbase = h0;                                      hstr = HID; }
        else        { hgbase = out + (size_t)tp * OUT_TSTR + dir * HID; hstr = OUT_ROW; }

        unsigned long long aR[2][2]  = {{0ull,0ull},{0ull,0ull}};
        unsigned long long aZ[2][2]  = {{0ull,0ull},{0ull,0ull}};
        unsigned long long aIN[2][2] = {{0ull,0ull},{0ull,0ull}};
        unsigned long long aHN[2][2] = {{0ull,0ull},{0ull,0ull}};
        float hp[2][2];   // [bb][jj]

        for (int c = 0; c < 4; ++c) {
            const int kb = c * 128;
            // ---- stage x[64][kb..kb+128) and h_prev[64][kb..kb+128) ----
            const float* xg = inp + (size_t)t * (BATCH * 512) + kb;
            const float* hg = hgbase + kb;
            #pragma unroll
            for (int i = 0; i < 16; ++i) {
                int idx = tid + i * THREADS;      // 0..2047
                int bb  = idx >> 5;
                int c4  = idx & 31;
                float4 xv4 = __ldg((const float4*)(xg + (size_t)bb * 512) + c4);
                *(float4*)(xs + bb * PAD_ROW + c4 * 4) = xv4;
                float4 hv4 = __ldg((const float4*)(hg + (size_t)bb * hstr) + c4);
                *(float4*)(hs + bb * PAD_ROW + c4 * 4) = hv4;
            }
            __syncthreads();

            if (c == jchunk) {
                #pragma unroll
                for (int bb = 0; bb < 2; ++bb) {
                    hp[bb][0] = hs[(b0 + bb) * PAD_ROW + j_in];
                    hp[bb][1] = hs[(b0 + bb) * PAD_ROW + j_in + 1];
                }
            }

            const float* xrow0 = xs + b0 * PAD_ROW;
            const float* hrow0 = hs + b0 * PAD_ROW;

            #pragma unroll 2
            for (int kk = 0; kk < 128; kk += 4) {
                ulonglong2 xv[2], hv[2];
                xv[0] = *(const ulonglong2*)(xrow0 + kk);
                xv[1] = *(const ulonglong2*)(xrow0 + PAD_ROW + kk);
                hv[0] = *(const ulonglong2*)(hrow0 + kk);
                hv[1] = *(const ulonglong2*)(hrow0 + PAD_ROW + kk);
                const int k = kb + kk;
                #pragma unroll
                for (int jj = 0; jj < 2; ++jj) {
                    const ulonglong2 wIr = *(const ulonglong2*)(wp[0  + jj] + k);
                    const ulonglong2 wIz = *(const ulonglong2*)(wp[2  + jj] + k);
                    const ulonglong2 wIn = *(const ulonglong2*)(wp[4  + jj] + k);
                    const ulonglong2 wHr = *(const ulonglong2*)(wp[6  + jj] + k);
                    const ulonglong2 wHz = *(const ulonglong2*)(wp[8  + jj] + k);
                    const ulonglong2 wHn = *(const ulonglong2*)(wp[10 + jj] + k);
                    #pragma unroll
                    for (int bb = 0; bb < 2; ++bb) {
                        fma2(aR[bb][jj],  xv[bb].x, wIr.x);
                        fma2(aR[bb][jj],  xv[bb].y, wIr.y);
                        fma2(aR[bb][jj],  hv[bb].x, wHr.x);
                        fma2(aR[bb][jj],  hv[bb].y, wHr.y);
                        fma2(aZ[bb][jj],  xv[bb].x, wIz.x);
                        fma2(aZ[bb][jj],  xv[bb].y, wIz.y);
                        fma2(aZ[bb][jj],  hv[bb].x, wHz.x);
                        fma2(aZ[bb][jj],  hv[bb].y, wHz.y);
                        fma2(aIN[bb][jj], xv[bb].x, wIn.x);
                        fma2(aIN[bb][jj], xv[bb].y, wIn.y);
                        fma2(aHN[bb][jj], hv[bb].x, wHn.x);
                        fma2(aHN[bb][jj], hv[bb].y, wHn.y);
                    }
                }
            }
            __syncthreads();   // before next chunk overwrites xs/hs
        }

        // ---- gates + outputs: 2 b x 2 j per thread ----
        #pragma unroll
        for (int bb = 0; bb < 2; ++bb) {
            float hn[2];
            #pragma unroll
            for (int jj = 0; jj < 2; ++jj) {
                const float2 r2  = unpk(aR[bb][jj]);
                const float2 z2  = unpk(aZ[bb][jj]);
                const float2 in2 = unpk(aIN[bb][jj]);
                const float2 hn2 = unpk(aHN[bb][jj]);
                const float sR  = r2.x  + r2.y  + bR[jj];
                const float sZ  = z2.x  + z2.y  + bZ[jj];
                const float sIN = in2.x + in2.y + bIN[jj];
                const float sHN = hn2.x + hn2.y + bHN[jj];
                const float r = sigmoidf_(sR);
                const float z = sigmoidf_(sZ);
                const float n = tanhf_(sIN + r * sHN);
                hn[jj] = (1.0f - z) * n + z * hp[bb][jj];
            }
            *(float2*)(out + (size_t)t * OUT_TSTR
                           + (size_t)(b0 + bb) * OUT_ROW + dir * HID + jA)
                = make_float2(hn[0], hn[1]);
            if (s == T_STEPS - 1)
                *(float2*)(hT_out + (size_t)(b0 + bb) * HID + jA)
                    = make_float2(hn[0], hn[1]);
        }

        // publish h to L2 + invalidate L1 (CCTL.IVALL), then grid barrier
        __threadfence();
        grid_barrier();
    }
}

extern "C" void kernel_launch(void* const* d_in, const int* in_sizes, int n_in,
                              void* d_out, int out_size)
{
    (void)in_sizes; (void)n_in; (void)out_size;
    const float* inp   = (const float*)d_in[0];
    const float* h0f   = (const float*)d_in[1];
    const float* h0b   = (const float*)d_in[2];
    const float* Wih_f = (const float*)d_in[3];
    const float* Whh_f = (const float*)d_in[4];
    const float* bih_f = (const float*)d_in[5];
    const float* bhh_f = (const float*)d_in[6];
    const float* Wih_b = (const float*)d_in[7];
    const float* Whh_b = (const float*)d_in[8];
    const float* bih_b = (const float*)d_in[9];
    const float* bhh_b = (const float*)d_in[10];
    float* out = (float*)d_out;

    const size_t smem_bytes =
        (6 * 8 * 512 + 2 * BATCH * PAD_ROW) * sizeof(float);   // 165,888 B
    cudaFuncSetAttribute(gru_bidir_kernel,
                         cudaFuncAttributeMaxDynamicSharedMemorySize,
                         (int)smem_bytes);

    gru_bidir_kernel<<<NBLK, THREADS, smem_bytes>>>(
        inp, h0f, h0b,
        Wih_f, Whh_f, bih_f, bhh_f,
        Wih_b, Whh_b, bih_b, bhh_b,
        out);
}